// round 1
// baseline (speedup 1.0000x reference)
#include <cuda_runtime.h>

#define BB 16
#define NN 2048
#define KK 16
#define CC 64
#define BN (BB * NN)

// ---------------- scratch (static device allocations are allowed) ----------
__device__ float g_A [BN * CC];   // x @ (W_dst @ W_attn)   (target-side logit term)
__device__ float g_Bv[BN * CC];   // x @ (W_src @ W_attn)   (source-side logit term)
__device__ float g_V [BN * CC];   // x @ W_val              (values)
__device__ int   g_nbr[BN * KK];  // knn indices (global point ids)
__device__ float g_Wda[CC * CC];  // W_dst @ W_attn
__device__ float g_Wsa[CC * CC];  // W_src @ W_attn
__device__ float g_Wpa[3 * CC];   // W_pos @ W_attn
__device__ float g_biasL[CC];     // b_pos @ W_attn + b_attn

// ---------------- k0: combine weights (1 block) -----------------------------
__global__ void combine_kernel(const float* __restrict__ W_pos,
                               const float* __restrict__ b_pos,
                               const float* __restrict__ W_attn,
                               const float* __restrict__ b_attn,
                               const float* __restrict__ W_src,
                               const float* __restrict__ W_dst) {
    __shared__ float sA[64 * 64];
    __shared__ float sD[64 * 64];
    __shared__ float sS[64 * 64];
    int tid = threadIdx.x;
    for (int idx = tid; idx < 4096; idx += 256) {
        sA[idx] = W_attn[idx];
        sD[idx] = W_dst[idx];
        sS[idx] = W_src[idx];
    }
    __syncthreads();
    for (int idx = tid; idx < 4096; idx += 256) {
        int k = idx >> 6, c = idx & 63;
        float a1 = 0.f, a2 = 0.f;
#pragma unroll 8
        for (int m = 0; m < 64; m++) {
            float w = sA[m * 64 + c];
            a1 = fmaf(sD[k * 64 + m], w, a1);
            a2 = fmaf(sS[k * 64 + m], w, a2);
        }
        g_Wda[idx] = a1;
        g_Wsa[idx] = a2;
    }
    for (int idx = tid; idx < 3 * 64; idx += 256) {
        int d = idx >> 6, c = idx & 63;
        float a = 0.f;
#pragma unroll 8
        for (int m = 0; m < 64; m++)
            a = fmaf(W_pos[d * 64 + m], sA[m * 64 + c], a);
        g_Wpa[idx] = a;
    }
    if (tid < 64) {
        float a = b_attn[tid];
#pragma unroll 8
        for (int m = 0; m < 64; m++)
            a = fmaf(b_pos[m], sA[m * 64 + tid], a);
        g_biasL[tid] = a;
    }
}

// ---------------- k1: fused per-point GEMMs  A,Bv,V = x @ {Wda,Wsa,Wval} ----
// Block: 64 points x 64 channels per matrix; 256 threads, 4x4 register tile.
__global__ void feat_gemm_kernel(const float* __restrict__ x,
                                 const float* __restrict__ W_val) {
    __shared__ float xs[64][68];   // transposed x tile (pad 68 for alignment)
    __shared__ float ws[64 * 64];  // current weight matrix
    int tid = threadIdx.x;
    int p0 = blockIdx.x * 64;

    for (int idx = tid; idx < 4096; idx += 256) {
        int p = idx >> 6, k = idx & 63;
        xs[k][p] = x[(p0 + p) * 64 + k];
    }

    int tx = tid & 15, ty = tid >> 4;

    for (int m = 0; m < 3; m++) {
        __syncthreads();  // (m==0) xs ready; (m>0) previous compute done
        const float* src = (m == 0) ? g_Wda : (m == 1) ? g_Wsa : W_val;
        for (int idx = tid; idx < 4096; idx += 256) ws[idx] = src[idx];
        __syncthreads();

        float acc[4][4];
#pragma unroll
        for (int i = 0; i < 4; i++)
#pragma unroll
            for (int j = 0; j < 4; j++) acc[i][j] = 0.f;

#pragma unroll 8
        for (int k = 0; k < 64; k++) {
            float4 xv = *(const float4*)&xs[k][ty * 4];
            float4 wv = *(const float4*)&ws[k * 64 + tx * 4];
            acc[0][0] = fmaf(xv.x, wv.x, acc[0][0]);
            acc[0][1] = fmaf(xv.x, wv.y, acc[0][1]);
            acc[0][2] = fmaf(xv.x, wv.z, acc[0][2]);
            acc[0][3] = fmaf(xv.x, wv.w, acc[0][3]);
            acc[1][0] = fmaf(xv.y, wv.x, acc[1][0]);
            acc[1][1] = fmaf(xv.y, wv.y, acc[1][1]);
            acc[1][2] = fmaf(xv.y, wv.z, acc[1][2]);
            acc[1][3] = fmaf(xv.y, wv.w, acc[1][3]);
            acc[2][0] = fmaf(xv.z, wv.x, acc[2][0]);
            acc[2][1] = fmaf(xv.z, wv.y, acc[2][1]);
            acc[2][2] = fmaf(xv.z, wv.z, acc[2][2]);
            acc[2][3] = fmaf(xv.z, wv.w, acc[2][3]);
            acc[3][0] = fmaf(xv.w, wv.x, acc[3][0]);
            acc[3][1] = fmaf(xv.w, wv.y, acc[3][1]);
            acc[3][2] = fmaf(xv.w, wv.z, acc[3][2]);
            acc[3][3] = fmaf(xv.w, wv.w, acc[3][3]);
        }

        float* op = (m == 0) ? g_A : (m == 1) ? g_Bv : g_V;
#pragma unroll
        for (int i = 0; i < 4; i++) {
            float4 r = make_float4(acc[i][0], acc[i][1], acc[i][2], acc[i][3]);
            *(float4*)&op[(p0 + ty * 4 + i) * 64 + tx * 4] = r;
        }
    }
}

// ---------------- k2: brute-force KNN, per-thread sorted top-16 -------------
__global__ void knn_kernel(const float* __restrict__ pos) {
    __shared__ float4 spos[NN];  // 32 KB
    int tid = threadIdx.x;
    int cloud = blockIdx.y;
    int base = cloud * NN;
    for (int idx = tid; idx < NN; idx += 256) {
        const float* p = pos + (size_t)(base + idx) * 3;
        spos[idx] = make_float4(p[0], p[1], p[2], 0.f);
    }
    __syncthreads();

    int il = blockIdx.x * 256 + tid;
    float4 pi = spos[il];

    float bd[KK];
    int bi[KK];
#pragma unroll
    for (int s = 0; s < KK; s++) { bd[s] = 3.4e38f; bi[s] = 0; }

    for (int j = 0; j < NN; j++) {
        float4 pj = spos[j];
        float dx = pi.x - pj.x, dy = pi.y - pj.y, dz = pi.z - pj.z;
        // match reference: squared diffs summed (no fma contraction)
        float d2 = __fadd_rn(__fadd_rn(__fmul_rn(dx, dx), __fmul_rn(dy, dy)),
                             __fmul_rn(dz, dz));
        if (d2 < bd[KK - 1] && j != il) {
            float d = d2;
            int id = j;
#pragma unroll
            for (int s = 0; s < KK; s++) {
                if (d < bd[s]) {
                    float td = bd[s]; bd[s] = d; d = td;
                    int ti = bi[s]; bi[s] = id; id = ti;
                }
            }
        }
    }
#pragma unroll
    for (int s = 0; s < KK; s++)
        g_nbr[(size_t)(base + il) * KK + s] = base + bi[s];
}

// ---------------- k3: edge kernel — warp per target, online softmax ---------
__global__ void edge_kernel(const float* __restrict__ pos,
                            const float* __restrict__ W_pos,
                            const float* __restrict__ b_pos,
                            float* __restrict__ out) {
    int tid = threadIdx.x;
    int lane = tid & 31;
    int warp = tid >> 5;
    int i = blockIdx.x * 8 + warp;
    int c0 = lane * 2;

    float2 Wpa0 = *(const float2*)&g_Wpa[0 * 64 + c0];
    float2 Wpa1 = *(const float2*)&g_Wpa[1 * 64 + c0];
    float2 Wpa2 = *(const float2*)&g_Wpa[2 * 64 + c0];
    float2 Wp0  = *(const float2*)&W_pos[0 * 64 + c0];
    float2 Wp1  = *(const float2*)&W_pos[1 * 64 + c0];
    float2 Wp2  = *(const float2*)&W_pos[2 * 64 + c0];
    float2 bp   = *(const float2*)&b_pos[c0];
    float2 bL   = *(const float2*)&g_biasL[c0];
    float2 Ai   = *(const float2*)&g_A[(size_t)i * 64 + c0];
    float basex = Ai.x + bL.x;
    float basey = Ai.y + bL.y;

    float pix = pos[i * 3 + 0];
    float piy = pos[i * 3 + 1];
    float piz = pos[i * 3 + 2];

    // lane j<16 carries neighbor j; lane>=16 carries self (used at j==16)
    int myn = (lane < KK) ? g_nbr[(size_t)i * KK + lane] : i;

    float sx = 0.f, sy = 0.f, ox = 0.f, oy = 0.f;

#pragma unroll 4
    for (int j = 0; j <= KK; j++) {
        int jj = __shfl_sync(0xffffffffu, myn, j);
        float pjx = pos[jj * 3 + 0];
        float pjy = pos[jj * 3 + 1];
        float pjz = pos[jj * 3 + 2];
        float dx = pix - pjx, dy = piy - pjy, dz = piz - pjz;

        float2 Bv = *(const float2*)&g_Bv[(size_t)jj * 64 + c0];
        float2 V  = *(const float2*)&g_V [(size_t)jj * 64 + c0];

        float lgx = basex - Bv.x + dx * Wpa0.x + dy * Wpa1.x + dz * Wpa2.x;
        float lgy = basey - Bv.y + dx * Wpa0.y + dy * Wpa1.y + dz * Wpa2.y;
        float px = __expf(lgx);
        float py = __expf(lgy);

        float dvx = dx * Wp0.x + dy * Wp1.x + dz * Wp2.x + bp.x;
        float dvy = dx * Wp0.y + dy * Wp1.y + dz * Wp2.y + bp.y;

        sx += px;
        sy += py;
        ox = fmaf(px, V.x + dvx, ox);
        oy = fmaf(py, V.y + dvy, oy);
    }

    float2 r;
    r.x = ox / sx;
    r.y = oy / sy;
    *(float2*)&out[(size_t)i * 64 + c0] = r;
}

// ---------------- launch -----------------------------------------------------
extern "C" void kernel_launch(void* const* d_in, const int* in_sizes, int n_in,
                              void* d_out, int out_size) {
    const float* x      = (const float*)d_in[0];
    const float* pos    = (const float*)d_in[1];
    // d_in[2] = batch (contiguous equal clouds; layout is implied, unused)
    const float* W_pos  = (const float*)d_in[3];
    const float* b_pos  = (const float*)d_in[4];
    const float* W_attn = (const float*)d_in[5];
    const float* b_attn = (const float*)d_in[6];
    const float* W_val  = (const float*)d_in[7];
    const float* W_src  = (const float*)d_in[8];
    const float* W_dst  = (const float*)d_in[9];
    float* out = (float*)d_out;

    combine_kernel<<<1, 256>>>(W_pos, b_pos, W_attn, b_attn, W_src, W_dst);
    feat_gemm_kernel<<<BN / 64, 256>>>(x, W_val);
    knn_kernel<<<dim3(NN / 256, BB), 256>>>(pos);
    edge_kernel<<<BN / 8, 256>>>(pos, W_pos, b_pos, out);
}

// round 2
// speedup vs baseline: 1.6021x; 1.6021x over previous
#include <cuda_runtime.h>

#define BB 16
#define NN 2048
#define KK 16
#define CC 64
#define BN (BB * NN)

#define BUFCAP 32   // per-thread smem hit-buffer entries
#define CHUNK 128   // candidates per buffered chunk
#define INITN 128   // direct-insertion warmup candidates

// ---------------- scratch ---------------------------------------------------
__device__ float g_A [BN * CC];   // x @ (W_dst @ W_attn)
__device__ float g_Bv[BN * CC];   // x @ (W_src @ W_attn)
__device__ float g_V [BN * CC];   // x @ W_val
__device__ int   g_nbr[BN * KK];  // knn indices (global point ids)
__device__ float g_Wda[CC * CC];
__device__ float g_Wsa[CC * CC];
__device__ float g_Wpa[3 * CC];
__device__ float g_biasL[CC];

// ---------------- k0: combine weights (17 blocks) ---------------------------
__global__ void combine_kernel(const float* __restrict__ W_pos,
                               const float* __restrict__ b_pos,
                               const float* __restrict__ W_attn,
                               const float* __restrict__ b_attn,
                               const float* __restrict__ W_src,
                               const float* __restrict__ W_dst) {
    int tid = threadIdx.x;
    int blk = blockIdx.x;
    if (blk < 16) {
        int r = tid >> 6, c = tid & 63;
        int k = blk * 4 + r;
        float a1 = 0.f, a2 = 0.f;
#pragma unroll 8
        for (int m = 0; m < 64; m++) {
            float w = W_attn[m * 64 + c];
            a1 = fmaf(W_dst[k * 64 + m], w, a1);
            a2 = fmaf(W_src[k * 64 + m], w, a2);
        }
        g_Wda[k * 64 + c] = a1;
        g_Wsa[k * 64 + c] = a2;
    } else {
        if (tid < 192) {
            int d = tid >> 6, c = tid & 63;
            float a = 0.f;
#pragma unroll 8
            for (int m = 0; m < 64; m++)
                a = fmaf(W_pos[d * 64 + m], W_attn[m * 64 + c], a);
            g_Wpa[tid] = a;
        } else {
            int c = tid - 192;
            float a = b_attn[c];
#pragma unroll 8
            for (int m = 0; m < 64; m++)
                a = fmaf(b_pos[m], W_attn[m * 64 + c], a);
            g_biasL[c] = a;
        }
    }
}

// ---------------- k1: fused per-point GEMMs --------------------------------
__global__ void feat_gemm_kernel(const float* __restrict__ x,
                                 const float* __restrict__ W_val) {
    __shared__ float xs[64][68];
    __shared__ float ws[64 * 64];
    int tid = threadIdx.x;
    int p0 = blockIdx.x * 64;

    for (int idx = tid; idx < 4096; idx += 256) {
        int p = idx >> 6, k = idx & 63;
        xs[k][p] = x[(p0 + p) * 64 + k];
    }

    int tx = tid & 15, ty = tid >> 4;

    for (int m = 0; m < 3; m++) {
        __syncthreads();
        const float* src = (m == 0) ? g_Wda : (m == 1) ? g_Wsa : W_val;
        for (int idx = tid; idx < 4096; idx += 256) ws[idx] = src[idx];
        __syncthreads();

        float acc[4][4];
#pragma unroll
        for (int i = 0; i < 4; i++)
#pragma unroll
            for (int j = 0; j < 4; j++) acc[i][j] = 0.f;

#pragma unroll 8
        for (int k = 0; k < 64; k++) {
            float4 xv = *(const float4*)&xs[k][ty * 4];
            float4 wv = *(const float4*)&ws[k * 64 + tx * 4];
            acc[0][0] = fmaf(xv.x, wv.x, acc[0][0]);
            acc[0][1] = fmaf(xv.x, wv.y, acc[0][1]);
            acc[0][2] = fmaf(xv.x, wv.z, acc[0][2]);
            acc[0][3] = fmaf(xv.x, wv.w, acc[0][3]);
            acc[1][0] = fmaf(xv.y, wv.x, acc[1][0]);
            acc[1][1] = fmaf(xv.y, wv.y, acc[1][1]);
            acc[1][2] = fmaf(xv.y, wv.z, acc[1][2]);
            acc[1][3] = fmaf(xv.y, wv.w, acc[1][3]);
            acc[2][0] = fmaf(xv.z, wv.x, acc[2][0]);
            acc[2][1] = fmaf(xv.z, wv.y, acc[2][1]);
            acc[2][2] = fmaf(xv.z, wv.z, acc[2][2]);
            acc[2][3] = fmaf(xv.z, wv.w, acc[2][3]);
            acc[3][0] = fmaf(xv.w, wv.x, acc[3][0]);
            acc[3][1] = fmaf(xv.w, wv.y, acc[3][1]);
            acc[3][2] = fmaf(xv.w, wv.z, acc[3][2]);
            acc[3][3] = fmaf(xv.w, wv.w, acc[3][3]);
        }

        float* op = (m == 0) ? g_A : (m == 1) ? g_Bv : g_V;
#pragma unroll
        for (int i = 0; i < 4; i++) {
            float4 r = make_float4(acc[i][0], acc[i][1], acc[i][2], acc[i][3]);
            *(float4*)&op[(p0 + ty * 4 + i) * 64 + tx * 4] = r;
        }
    }
}

// ---------------- k2: KNN with buffered hits --------------------------------
__device__ __forceinline__ void insert16(float (&bd)[KK], int (&bi)[KK],
                                         float d, int id) {
#pragma unroll
    for (int s = 0; s < KK; s++) {
        bool p = d < bd[s];
        float nbd = p ? d : bd[s];
        float nd  = p ? bd[s] : d;
        int   nbi = p ? id : bi[s];
        int   nid = p ? bi[s] : id;
        bd[s] = nbd; d = nd; bi[s] = nbi; id = nid;
    }
}

__global__ void __launch_bounds__(256) knn_kernel(const float* __restrict__ pos) {
    extern __shared__ char ksm[];
    float4* spos = (float4*)ksm;                     // 32 KB
    uint2*  buf  = (uint2*)(ksm + NN * 16);          // [BUFCAP][256] = 64 KB

    int tid = threadIdx.x;
    int base = blockIdx.y * NN;
    for (int idx = tid; idx < NN; idx += 256) {
        const float* p = pos + (size_t)(base + idx) * 3;
        spos[idx] = make_float4(p[0], p[1], p[2], 0.f);
    }
    __syncthreads();

    int il = blockIdx.x * 256 + tid;
    float4 pi = spos[il];

    float bd[KK];
    int bi[KK];
#pragma unroll
    for (int s = 0; s < KK; s++) { bd[s] = 3.4e38f; bi[s] = 0; }

    // warmup: direct insertion for first INITN candidates
#pragma unroll 4
    for (int j = 0; j < INITN; j++) {
        float4 pj = spos[j];
        float dx = pi.x - pj.x, dy = pi.y - pj.y, dz = pi.z - pj.z;
        float d2 = fmaf(dx, dx, fmaf(dy, dy, dz * dz));
        if (d2 < bd[KK - 1] && j != il) insert16(bd, bi, d2, j);
    }

    // buffered chunks
    int cnt = 0;
    for (int c = INITN; c < NN; c += CHUNK) {
#pragma unroll 4
        for (int j = c; j < c + CHUNK; j++) {
            float4 pj = spos[j];
            float dx = pi.x - pj.x, dy = pi.y - pj.y, dz = pi.z - pj.z;
            float d2 = fmaf(dx, dx, fmaf(dy, dy, dz * dz));
            if (d2 < bd[KK - 1] && j != il) {
                if (cnt < BUFCAP) {
                    buf[cnt * 256 + tid] = make_uint2(__float_as_uint(d2), (unsigned)j);
                    cnt++;
                } else {
                    insert16(bd, bi, d2, j);  // rare overflow fallback
                }
            }
        }
        unsigned wmax = __reduce_max_sync(0xffffffffu, (unsigned)cnt);
        for (unsigned m = 0; m < wmax; m++) {
            if ((int)m < cnt) {
                uint2 e = buf[m * 256 + tid];
                float d2 = __uint_as_float(e.x);
                if (d2 < bd[KK - 1]) insert16(bd, bi, d2, (int)e.y);
            }
        }
        cnt = 0;
    }

#pragma unroll
    for (int s = 0; s < KK; s++)
        g_nbr[(size_t)(base + il) * KK + s] = base + bi[s];
}

// ---------------- k3: edge kernel -------------------------------------------
__global__ void edge_kernel(const float* __restrict__ pos,
                            const float* __restrict__ W_pos,
                            const float* __restrict__ b_pos,
                            float* __restrict__ out) {
    int tid = threadIdx.x;
    int lane = tid & 31;
    int warp = tid >> 5;
    int i = blockIdx.x * 8 + warp;
    int c0 = lane * 2;

    float2 Wpa0 = *(const float2*)&g_Wpa[0 * 64 + c0];
    float2 Wpa1 = *(const float2*)&g_Wpa[1 * 64 + c0];
    float2 Wpa2 = *(const float2*)&g_Wpa[2 * 64 + c0];
    float2 Wp0  = *(const float2*)&W_pos[0 * 64 + c0];
    float2 Wp1  = *(const float2*)&W_pos[1 * 64 + c0];
    float2 Wp2  = *(const float2*)&W_pos[2 * 64 + c0];
    float2 bp   = *(const float2*)&b_pos[c0];
    float2 bL   = *(const float2*)&g_biasL[c0];
    float2 Ai   = *(const float2*)&g_A[(size_t)i * 64 + c0];
    float basex = Ai.x + bL.x;
    float basey = Ai.y + bL.y;

    float pix = pos[i * 3 + 0];
    float piy = pos[i * 3 + 1];
    float piz = pos[i * 3 + 2];

    // lane j<16 carries neighbor j; lane 16 carries self
    int myn = (lane < KK) ? g_nbr[(size_t)i * KK + lane] : i;
    float mpx = pos[myn * 3 + 0];
    float mpy = pos[myn * 3 + 1];
    float mpz = pos[myn * 3 + 2];

    float sx = 0.f, sy = 0.f, ox = 0.f, oy = 0.f;

#pragma unroll 4
    for (int j = 0; j <= KK; j++) {
        int jj  = __shfl_sync(0xffffffffu, myn, j);
        float pjx = __shfl_sync(0xffffffffu, mpx, j);
        float pjy = __shfl_sync(0xffffffffu, mpy, j);
        float pjz = __shfl_sync(0xffffffffu, mpz, j);
        float dx = pix - pjx, dy = piy - pjy, dz = piz - pjz;

        float2 Bv = *(const float2*)&g_Bv[(size_t)jj * 64 + c0];
        float2 V  = *(const float2*)&g_V [(size_t)jj * 64 + c0];

        float lgx = basex - Bv.x + dx * Wpa0.x + dy * Wpa1.x + dz * Wpa2.x;
        float lgy = basey - Bv.y + dx * Wpa0.y + dy * Wpa1.y + dz * Wpa2.y;
        float px = __expf(lgx);
        float py = __expf(lgy);

        float dvx = dx * Wp0.x + dy * Wp1.x + dz * Wp2.x + bp.x;
        float dvy = dx * Wp0.y + dy * Wp1.y + dz * Wp2.y + bp.y;

        sx += px;
        sy += py;
        ox = fmaf(px, V.x + dvx, ox);
        oy = fmaf(py, V.y + dvy, oy);
    }

    float2 r;
    r.x = ox / sx;
    r.y = oy / sy;
    *(float2*)&out[(size_t)i * 64 + c0] = r;
}

// ---------------- launch -----------------------------------------------------
extern "C" void kernel_launch(void* const* d_in, const int* in_sizes, int n_in,
                              void* d_out, int out_size) {
    const float* x      = (const float*)d_in[0];
    const float* pos    = (const float*)d_in[1];
    const float* W_pos  = (const float*)d_in[3];
    const float* b_pos  = (const float*)d_in[4];
    const float* W_attn = (const float*)d_in[5];
    const float* b_attn = (const float*)d_in[6];
    const float* W_val  = (const float*)d_in[7];
    const float* W_src  = (const float*)d_in[8];
    const float* W_dst  = (const float*)d_in[9];
    float* out = (float*)d_out;

    const int knn_smem = NN * 16 + BUFCAP * 256 * 8;  // 98304 B
    cudaFuncSetAttribute(knn_kernel, cudaFuncAttributeMaxDynamicSharedMemorySize,
                         knn_smem);

    combine_kernel<<<17, 256>>>(W_pos, b_pos, W_attn, b_attn, W_src, W_dst);
    feat_gemm_kernel<<<BN / 64, 256>>>(x, W_val);
    knn_kernel<<<dim3(NN / 256, BB), 256, knn_smem>>>(pos);
    edge_kernel<<<BN / 8, 256>>>(pos, W_pos, b_pos, out);
}